// round 13
// baseline (speedup 1.0000x reference)
#include <cuda_runtime.h>
#include <math.h>
#include <stdint.h>

#define TT 512
#define BB 64
#define II 512
#define HH 512

// packed fp32x2 FMA: d.lo += a.lo*b.lo, d.hi += a.hi*b.hi  (Blackwell f32x2)
#define FMA2(acc, a, b) \
    asm("fma.rn.f32x2 %0, %1, %2, %0;" : "+l"(acc) : "l"(a), "l"(b))

__device__ __forceinline__ float2 f32x2_unpack(unsigned long long v) {
    float2 f;
    asm("mov.b64 {%0, %1}, %2;" : "=f"(f.x), "=f"(f.y) : "l"(v));
    return f;
}
__device__ __forceinline__ unsigned long long f32_dup2(float f) {
    unsigned long long d; unsigned int u = __float_as_uint(f);
    asm("mov.b64 %0, {%1, %1};" : "=l"(d) : "r"(u));
    return d;
}

// ---------------------------------------------------------------------------
// Phase 1: C[M=T*B, N=H] = X[M,K] @ W[N,K]^T + (b_ih + b_hh), FFMA2 inner loop
// ---------------------------------------------------------------------------
__global__ __launch_bounds__(256) void gemm_xproj(
    const float* __restrict__ X, const float* __restrict__ W,
    const float* __restrict__ bih, const float* __restrict__ bhh,
    float* __restrict__ C)
{
    __shared__ __align__(16) float As[16][132];
    __shared__ __align__(16) float Bs[16][68];

    const int bm  = blockIdx.x;
    const int bn  = blockIdx.y;
    const int tid = threadIdx.x;
    const int tx  = tid & 15;
    const int ty  = tid >> 4;

    const int arow0 = bm * 128;
    const int brow0 = bn * 64;

    // acc2[i2][j] packs rows (2*i2, 2*i2+1) of this thread's 8-row tile
    unsigned long long acc2[4][4];
#pragma unroll
    for (int i = 0; i < 4; i++)
#pragma unroll
        for (int j = 0; j < 4; j++) acc2[i][j] = 0ull;

    for (int kt = 0; kt < II; kt += 16) {
#pragma unroll
        for (int i = 0; i < 2; i++) {
            int idx = tid + i * 256;
            int row = idx >> 2;
            int kq  = idx & 3;
            float4 v = *(const float4*)(X + (size_t)(arow0 + row) * II + kt + kq * 4);
            As[kq * 4 + 0][row] = v.x;
            As[kq * 4 + 1][row] = v.y;
            As[kq * 4 + 2][row] = v.z;
            As[kq * 4 + 3][row] = v.w;
        }
        {
            int row = tid >> 2;
            int kq  = tid & 3;
            float4 v = *(const float4*)(W + (size_t)(brow0 + row) * II + kt + kq * 4);
            Bs[kq * 4 + 0][row] = v.x;
            Bs[kq * 4 + 1][row] = v.y;
            Bs[kq * 4 + 2][row] = v.z;
            Bs[kq * 4 + 3][row] = v.w;
        }
        __syncthreads();

#pragma unroll
        for (int k = 0; k < 16; k++) {
            const ulonglong2* ap = (const ulonglong2*)&As[k][ty * 8];
            ulonglong2 aA = ap[0], aB = ap[1];
            unsigned long long a2[4] = {aA.x, aA.y, aB.x, aB.y};
            float4 bv = *(const float4*)&Bs[k][tx * 4];
            unsigned long long b2[4] = {f32_dup2(bv.x), f32_dup2(bv.y),
                                        f32_dup2(bv.z), f32_dup2(bv.w)};
#pragma unroll
            for (int i = 0; i < 4; i++)
#pragma unroll
                for (int j = 0; j < 4; j++)
                    FMA2(acc2[i][j], a2[i], b2[j]);
        }
        __syncthreads();
    }

    float4 bias;
    {
        int n = brow0 + tx * 4;
        bias.x = bih[n + 0] + bhh[n + 0];
        bias.y = bih[n + 1] + bhh[n + 1];
        bias.z = bih[n + 2] + bhh[n + 2];
        bias.w = bih[n + 3] + bhh[n + 3];
    }
#pragma unroll
    for (int i2 = 0; i2 < 4; i2++) {
        float2 p0 = f32x2_unpack(acc2[i2][0]);
        float2 p1 = f32x2_unpack(acc2[i2][1]);
        float2 p2 = f32x2_unpack(acc2[i2][2]);
        float2 p3 = f32x2_unpack(acc2[i2][3]);
        int m0 = arow0 + ty * 8 + 2 * i2;
        float4 e = make_float4(p0.x + bias.x, p1.x + bias.y, p2.x + bias.z, p3.x + bias.w);
        float4 o = make_float4(p0.y + bias.x, p1.y + bias.y, p2.y + bias.z, p3.y + bias.w);
        *(float4*)(C + (size_t)m0 * HH + brow0 + tx * 4) = e;
        *(float4*)(C + (size_t)(m0 + 1) * HH + brow0 + tx * 4) = o;
    }
}

// ---------------------------------------------------------------------------
// Phase 2 v6: cluster recurrence, FFMA2 compute + DSMEM-mbarrier sync.
// 16 clusters x 8 CTAs x 512 threads; CTA rank r owns columns [64r,64r+64);
// cluster owns 4 batches; W_hh in packed-f32x2 registers.
// Per step: prefetch xp -> mbarrier wait (acquire.cluster, ~60-90 cyc, no
// L1 flush) -> 128 FFMA2 from smem -> butterfly reduce -> tanh -> stage ->
// exactly 512 v4 remote stores (1/thread) -> bar.sync -> 8 remote
// release-arrives. Two barriers (one per h buffer) make phases unambiguous.
// ---------------------------------------------------------------------------
#define GRP      36                  // 32 data + 4 pad floats
#define BROW     (16 * GRP)          // 576 floats per batch row
#define BUFFLT   (4 * BROW)          // 2304 floats per buffer
#define BUFBYTES (BUFFLT * 4)        // 9216 B

__device__ __forceinline__ float tanh_fast(float x) {
    float xc = fminf(fmaxf(x, -15.0f), 15.0f);
    float e  = __expf(2.0f * xc);
    return __fdividef(e - 1.0f, e + 1.0f);
}

__device__ __forceinline__ void mbar_waitc(uint32_t mbar, uint32_t parity) {
    asm volatile(
        "{\n\t"
        ".reg .pred P;\n\t"
        "WL_%=:\n\t"
        "mbarrier.try_wait.parity.acquire.cluster.shared::cta.b64 P, [%0], %1, 0x989680;\n\t"
        "@P bra WD_%=;\n\t"
        "bra WL_%=;\n\t"
        "WD_%=:\n\t"
        "}" :: "r"(mbar), "r"(parity) : "memory");
}

__global__ void __cluster_dims__(8, 1, 1) __launch_bounds__(512, 1)
rnn_cluster6(const float* __restrict__ Whh, float* __restrict__ out)
{
    __shared__ __align__(16) float hs[2][BUFFLT];   // 18432 B
    __shared__ __align__(16) float stg[4 * 72];     // staging [batch][72]
    __shared__ __align__(8)  unsigned long long mbar[2];

    const int cid = blockIdx.x >> 3;    // cluster id 0..15
    const int r   = blockIdx.x & 7;     // rank 0..7
    const int tid = threadIdx.x;
    const int jg  = tid >> 5;           // 0..15 column group (4 cols)
    const int kc  = tid & 31;           // 0..31 k-chunk (= lane id)
    const int gb0 = cid * 4;

    // W_hh: 4 rows x 16 k -> packed f32x2 registers (resident all steps)
    unsigned long long w2[4][8];
#pragma unroll
    for (int c = 0; c < 4; c++) {
        const ulonglong2* wp =
            (const ulonglong2*)(Whh + (size_t)(r * 64 + jg * 4 + c) * HH + kc * 16);
#pragma unroll
        for (int i = 0; i < 4; i++) {
            ulonglong2 u = wp[i];
            w2[c][2 * i]     = u.x;
            w2[c][2 * i + 1] = u.y;
        }
    }

    // butterfly result mapping (identical to v4/v5)
    const int cres  = 2 * ((kc >> 4) & 1) + ((kc >> 1) & 1);
    const int bres  = 2 * ((kc >> 3) & 1) + ((kc >> 2) & 1);
    const int jlres = jg * 4 + cres;
    const int jres  = r * 64 + jlres;
    const int gbres = gb0 + bres;
    const bool writer = (kc & 1) == 0;
    const int stg_slot = bres * 72 + ((jlres >> 5) * 36) + (jlres & 31);

    // mbarriers: count 8 = one release-arrive per producer CTA per phase
    const uint32_t mb_base = (uint32_t)__cvta_generic_to_shared(mbar);
    if (tid < 2)
        asm volatile("mbarrier.init.shared.b64 [%0], %1;"
                     :: "r"(mb_base + tid * 8), "r"(8u) : "memory");

    // fanout descriptor: exactly one v4 store per thread (pads skipped)
    // tid -> target = tid>>6; q=tid&63: b=q>>4, gi=(q>>3)&1, f=q&7
    const uint32_t hs_base = (uint32_t)__cvta_generic_to_shared(hs);
    const int tgt = tid >> 6;
    const int qq  = tid & 63;
    const int fb  = qq >> 4;
    const int gi  = (qq >> 3) & 1;
    const int ff  = qq & 7;
    const int dstf = fb * BROW + (2 * r + gi) * GRP + ff * 4;
    const int srcf = fb * 72 + gi * 36 + ff * 4;
    uint32_t rdst;
    asm volatile("mapa.shared::cluster.u32 %0, %1, %2;"
                 : "=r"(rdst) : "r"(hs_base + (uint32_t)dstf * 4u), "r"((uint32_t)tgt));
    uint32_t rmb = 0;
    if (tid < 8)
        asm volatile("mapa.shared::cluster.u32 %0, %1, %2;"
                     : "=r"(rmb) : "r"(mb_base), "r"((uint32_t)tid));

    __syncthreads();
    asm volatile("barrier.cluster.arrive.aligned;" ::: "memory");
    asm volatile("barrier.cluster.wait.aligned;"   ::: "memory");

    const float* xp_base = out + (size_t)gbres * HH + jres;
    float*       st_base = out + (size_t)gbres * HH + jres;

    // ---- t = 0 : h0 = 0 -> h = tanh(xproj); fanout into buffer 0 ----
    float h = tanh_fast(__ldg(xp_base));
    if (writer) {
        st_base[0] = h;
        stg[stg_slot] = h;
    }
    __syncthreads();
    {
        uint4 v = *(const uint4*)(stg + srcf);
        asm volatile("st.shared::cluster.v4.b32 [%0], {%1,%2,%3,%4};"
                     :: "r"(rdst), "r"(v.x), "r"(v.y), "r"(v.z), "r"(v.w) : "memory");
    }
    __syncthreads();
    if (tid < 8)
        asm volatile("mbarrier.arrive.release.cluster.shared::cluster.b64 _, [%0];"
                     :: "r"(rmb) : "memory");

    const bool s16 = (kc & 16) != 0;
    const bool s8  = (kc & 8)  != 0;
    const bool s4  = (kc & 4)  != 0;
    const bool s2  = (kc & 2)  != 0;

    const float* hrd = &hs[0][0] + (kc >> 1) * GRP + (kc & 1) * 16;

    for (int t = 1; t < TT; t++) {
        // prefetch xp BEFORE the wait: overlaps barrier latency
        float xp = __ldg(xp_base + (size_t)t * BB * HH);

        const int      rb  = (t - 1) & 1;                    // buffer to read
        const uint32_t par = (uint32_t)(((t - 1) >> 1) & 1); // its phase parity
        mbar_waitc(mb_base + (uint32_t)rb * 8u, par);

        // packed partial dots pd2[c][b] over k in [16kc, 16kc+16)
        unsigned long long pd2[4][4];
#pragma unroll
        for (int c = 0; c < 4; c++)
#pragma unroll
            for (int b = 0; b < 4; b++) pd2[c][b] = 0ull;

        const float* hb = hrd + rb * BUFFLT;
#pragma unroll
        for (int b = 0; b < 4; b++) {
#pragma unroll
            for (int i = 0; i < 4; i++) {
                ulonglong2 hv = *(const ulonglong2*)(hb + b * BROW + i * 4);
#pragma unroll
                for (int c = 0; c < 4; c++) {
                    FMA2(pd2[c][b], hv.x, w2[c][2 * i]);
                    FMA2(pd2[c][b], hv.y, w2[c][2 * i + 1]);
                }
            }
        }
        float pd[4][4];
#pragma unroll
        for (int c = 0; c < 4; c++)
#pragma unroll
            for (int b = 0; b < 4; b++) {
                float2 p = f32x2_unpack(pd2[c][b]);
                pd[c][b] = p.x + p.y;
            }

        // value-splitting butterfly over the 32 kc lanes (16 shfl)
        float q[2][4];
#pragma unroll
        for (int c1 = 0; c1 < 2; c1++)
#pragma unroll
            for (int b = 0; b < 4; b++) {
                float send = s16 ? pd[c1][b]     : pd[2 + c1][b];
                float keep = s16 ? pd[2 + c1][b] : pd[c1][b];
                q[c1][b] = keep + __shfl_xor_sync(0xffffffffu, send, 16);
            }
        float r2[2][2];
#pragma unroll
        for (int c1 = 0; c1 < 2; c1++)
#pragma unroll
            for (int b1 = 0; b1 < 2; b1++) {
                float send = s8 ? q[c1][b1]     : q[c1][2 + b1];
                float keep = s8 ? q[c1][2 + b1] : q[c1][b1];
                r2[c1][b1] = keep + __shfl_xor_sync(0xffffffffu, send, 8);
            }
        float r3[2];
#pragma unroll
        for (int c1 = 0; c1 < 2; c1++) {
            float send = s4 ? r2[c1][0] : r2[c1][1];
            float keep = s4 ? r2[c1][1] : r2[c1][0];
            r3[c1] = keep + __shfl_xor_sync(0xffffffffu, send, 4);
        }
        {
            float send = s2 ? r3[0] : r3[1];
            float keep = s2 ? r3[1] : r3[0];
            r3[0] = keep + __shfl_xor_sync(0xffffffffu, send, 2);
        }
        float dot = r3[0] + __shfl_xor_sync(0xffffffffu, r3[0], 1);

        h = tanh_fast(dot + xp);

        if (writer) {
            st_base[(size_t)t * BB * HH] = h;
            stg[stg_slot] = h;
        }
        __syncthreads();

        if (t < TT - 1) {   // last step's h is read by nobody: skip fanout
            const int wbuf = t & 1;
            uint4 v = *(const uint4*)(stg + srcf);
            asm volatile("st.shared::cluster.v4.b32 [%0], {%1,%2,%3,%4};"
                         :: "r"(rdst + (uint32_t)wbuf * BUFBYTES),
                            "r"(v.x), "r"(v.y), "r"(v.z), "r"(v.w) : "memory");
            __syncthreads();
            if (tid < 8)
                asm volatile("mbarrier.arrive.release.cluster.shared::cluster.b64 _, [%0];"
                             :: "r"(rmb + (uint32_t)wbuf * 8u) : "memory");
        }
    }

    // ---- h_n tail ----
    if (writer)
        out[(size_t)TT * BB * HH + (size_t)gbres * HH + jres] = h;
}

// ---------------------------------------------------------------------------
// Launch
// Inputs: x [T,B,I], w_ih [H,I], w_hh [H,H], b_ih [H], b_hh [H]
// Output: output [T,B,H] ++ h_n [B,H]  (fp32)
// ---------------------------------------------------------------------------
extern "C" void kernel_launch(void* const* d_in, const int* in_sizes, int n_in,
                              void* d_out, int out_size)
{
    (void)in_sizes; (void)n_in; (void)out_size;
    const float* x    = (const float*)d_in[0];
    const float* w_ih = (const float*)d_in[1];
    const float* w_hh = (const float*)d_in[2];
    const float* b_ih = (const float*)d_in[3];
    const float* b_hh = (const float*)d_in[4];
    float* out = (float*)d_out;

    // Phase 1: xproj into d_out
    dim3 g1((TT * BB) / 128, HH / 64);
    gemm_xproj<<<g1, 256>>>(x, w_ih, b_ih, b_hh, out);

    // Phase 2: cluster recurrence (128 CTAs = 16 clusters of 8)
    rnn_cluster6<<<128, 512>>>(w_hh, out);
}